// round 16
// baseline (speedup 1.0000x reference)
#include <cuda_runtime.h>
#include <cuda_bf16.h>

#define NK    64
#define PLANE (256 * 64)
#define CH    (256 * 256 * 64)
#define NSEG  9
#define NBLK  (2 * 16 * NSEG)   // 288

// Zero-initialized at module load; finalize self-resets them after each run.
__device__ double g_div_sum;
__device__ double g_smooth_sum;
__device__ float  g_sbin[2][63];
__device__ float  g_qbin[2][63];
__device__ unsigned g_done;

__device__ __forceinline__ void pf_l2(const void* p) {
    asm volatile("prefetch.global.L2 [%0];" :: "l"(p));
}

__device__ __forceinline__ float cell_term(
    float p0a, float p0b, float p1a, float p1b,
    float q0a, float q0b, float q1a, float q1b,
    float sza, float szb, float Pva, float Pvb,
    float sxa, float sxb, float sya, float syb,
    float d00, float d01, float d10, float d11)
{
    float A1 = (p1a + p1b) * (d10 + d11);
    float A2 = (p0a + p0b) * (d00 + d01);
    float A3 = (q1a + q1b) * (d01 + d11);
    float A4 = (q0a + q0b) * (d00 + d10);
    float num = 0.125f * ((A1 - A2) + (A3 - A4))
              + 0.25f * (szb - sza) + (Pvb - Pva);
    float sxx = sxa + sxb;
    float syy = sya + syb;
    float szz = sza + szb;
    float den = 0.015625f * (sxx * sxx + syy * syy + szz * szz) + 1e-10f;
    return __fdividef(num * num, den);
}

struct Row {
    float bxj[4], bxp[4], byj[4], byp[4], szr[4];
    float zj[5], zp[5];
};

// Raw staged loads for one row (9 float4 = 36 regs while in flight).
struct Raw {
    float4 zm, zj, zp, xj, xp, yj, yp, wj, wp;
};

// Issue the 9 LDG.128 for row `gic` (pre-clamped) + L2 prefetch 2 ahead.
__device__ __forceinline__ Raw load_row(
    int gic, int gpf, bool pfl,
    const float* __restrict__ zb, const float* __restrict__ xb,
    const float* __restrict__ yb, const float* __restrict__ wb,
    size_t offj, size_t offm, size_t offp)
{
    size_t ro = (size_t)gic * PLANE;
    Raw r;
    r.zm = *(const float4*)(zb + ro + offm);
    r.zj = *(const float4*)(zb + ro + offj);
    r.zp = *(const float4*)(zb + ro + offp);
    r.xj = *(const float4*)(xb + ro + offj);
    r.xp = *(const float4*)(xb + ro + offp);
    r.yj = *(const float4*)(yb + ro + offj);
    r.yp = *(const float4*)(yb + ro + offp);
    r.wj = *(const float4*)(wb + ro + offj);
    r.wp = *(const float4*)(wb + ro + offp);
    if (pfl) {
        size_t rn = (size_t)gpf * PLANE;
        pf_l2(zb + rn + offj);
        pf_l2(xb + rn + offj);
        pf_l2(yb + rn + offj);
        pf_l2(wb + rn + offj);
    }
    return r;
}

// Compute one row-step from staged loads. Identical math to the R14 step.
template<bool INT>
__device__ __forceinline__ void compute(
    Row& P, Row& C, const Raw& W, int gi, int i0, int i1, bool jdiv, bool jsm,
    bool g1, bool l15, int kk,
    float d2C2[4], float d2C1[4], float& d2p1, float& d2n1,
    float d2L1[4], float d2R1[4],
    float sS[4], float sQ[4], float& accD, float& accL)
{
    const unsigned FM = 0xffffffffu;

    float zm[5];
    zm[0] = W.zm.x; zm[1] = W.zm.y; zm[2] = W.zm.z; zm[3] = W.zm.w;
    C.zj[0] = W.zj.x; C.zj[1] = W.zj.y; C.zj[2] = W.zj.z; C.zj[3] = W.zj.w;
    C.zp[0] = W.zp.x; C.zp[1] = W.zp.y; C.zp[2] = W.zp.z; C.zp[3] = W.zp.w;
    C.bxj[0] = W.xj.x; C.bxj[1] = W.xj.y; C.bxj[2] = W.xj.z; C.bxj[3] = W.xj.w;
    C.bxp[0] = W.xp.x; C.bxp[1] = W.xp.y; C.bxp[2] = W.xp.z; C.bxp[3] = W.xp.w;
    C.byj[0] = W.yj.x; C.byj[1] = W.yj.y; C.byj[2] = W.yj.z; C.byj[3] = W.yj.w;
    C.byp[0] = W.yp.x; C.byp[1] = W.yp.y; C.byp[2] = W.yp.z; C.byp[3] = W.yp.w;
    C.szr[0] = W.wj.x + W.wp.x; C.szr[1] = W.wj.y + W.wp.y;
    C.szr[2] = W.wj.z + W.wp.z; C.szr[3] = W.wj.w + W.wp.w;

    zm[4]   = __shfl_down_sync(FM, zm[0],   1, 16);
    C.zj[4] = __shfl_down_sync(FM, C.zj[0], 1, 16);
    C.zp[4] = __shfl_down_sync(FM, C.zp[0], 1, 16);

    float dzc[4], d2C0[4], d2L0[4], d2R0[4];
    #pragma unroll
    for (int t = 0; t < 4; t++) {
        float dc = C.zj[t + 1] - C.zj[t]; dzc[t] = dc; d2C0[t] = dc * dc;
        float dl = zm[t + 1]   - zm[t];   d2L0[t] = dl * dl;
        float dr = C.zp[t + 1] - C.zp[t]; d2R0[t] = dr * dr;
    }
    float d2p0 = __shfl_up_sync(FM, d2C0[3], 1, 16);
    float d2n0 = __shfl_down_sync(FM, d2C0[0], 1, 16);

    bool ownC = INT ? true : (gi >= i0 && gi < i1);
    if (ownC) {
        #pragma unroll
        for (int t = 0; t < 4; t++) { sS[t] += dzc[t]; sQ[t] += d2C0[t]; }
    }

    float p0[4], p1[4], q0[4], q1[4], sz[4], Pv[4], sx[4], sy[4];
    #pragma unroll
    for (int t = 0; t < 4; t++) {
        p0[t] = P.bxj[t] + P.bxp[t];
        p1[t] = C.bxj[t] + C.bxp[t];
        q0[t] = P.byj[t] + C.byj[t];
        q1[t] = P.byp[t] + C.byp[t];
        sz[t] = P.szr[t] + C.szr[t];
        float A = P.zj[t] - C.zj[t];
        float B = P.zp[t] - C.zp[t];
        Pv[t] = (P.bxj[t] * A + P.bxp[t] * B + p1[t] * (A + B)
               + (C.byj[t] + C.byp[t] + P.byp[t]) * (C.zj[t] - C.zp[t])
               + (P.byj[t] + P.byp[t] + C.byp[t]) * (P.zj[t] - P.zp[t]))
               * (1.f / 6.f);
        sx[t] = p0[t] + p1[t];
        sy[t] = q0[t] + q1[t];
    }
    float p0_4 = __shfl_down_sync(FM, p0[0], 1, 16);
    float p1_4 = __shfl_down_sync(FM, p1[0], 1, 16);
    float q0_4 = __shfl_down_sync(FM, q0[0], 1, 16);
    float q1_4 = __shfl_down_sync(FM, q1[0], 1, 16);
    float sz_4 = __shfl_down_sync(FM, sz[0], 1, 16);
    float Pv_4 = __shfl_down_sync(FM, Pv[0], 1, 16);
    float sx_4 = p0_4 + p1_4;
    float sy_4 = q0_4 + q1_4;

    bool ownP = INT ? true : (gi - 1 >= i0 && gi - 1 < i1 && gi <= 255);
    if (ownP && jdiv) {
        #pragma unroll
        for (int t = 0; t < 3; t++) {
            float d00 = fabsf(P.zj[t + 1] - P.zj[t]);
            float d01 = fabsf(P.zp[t + 1] - P.zp[t]);
            float d10 = fabsf(dzc[t]);
            float d11 = fabsf(C.zp[t + 1] - C.zp[t]);
            accD += cell_term(p0[t], p0[t + 1], p1[t], p1[t + 1],
                              q0[t], q0[t + 1], q1[t], q1[t + 1],
                              sz[t], sz[t + 1], Pv[t], Pv[t + 1],
                              sx[t], sx[t + 1], sy[t], sy[t + 1],
                              d00, d01, d10, d11);
        }
        if (l15) {
            float d00 = fabsf(P.zj[4] - P.zj[3]);
            float d01 = fabsf(P.zp[4] - P.zp[3]);
            float d10 = fabsf(dzc[3]);
            float d11 = fabsf(C.zp[4] - C.zp[3]);
            accD += cell_term(p0[3], p0_4, p1[3], p1_4,
                              q0[3], q0_4, q1[3], q1_4,
                              sz[3], sz_4, Pv[3], Pv_4,
                              sx[3], sx_4, sy[3], sy_4,
                              d00, d01, d10, d11);
        }
    }

    int ic = gi - 1;
    bool smok;
    if (INT) smok = (ic >= 1) && (ic <= 254) && jsm;
    else     smok = (ic >= i0) && (ic < i1) && (ic >= 1) && (ic <= 254)
                    && (gi <= 255) && jsm;
    if (smok) {
        if (g1) {
            float lap = 6.f * d2C1[0] - d2C2[0] - d2C0[0]
                      - d2L1[0] - d2R1[0] - d2p1 - d2C1[1];
            accL += lap * lap;
        }
        {
            float lap = 6.f * d2C1[1] - d2C2[1] - d2C0[1]
                      - d2L1[1] - d2R1[1] - d2C1[0] - d2C1[2];
            accL += lap * lap;
        }
        if (l15) {
            float lap2 = 6.f * d2C1[2] - d2C2[2] - d2C0[2]
                       - d2L1[2] - d2R1[2] - d2C1[1] - d2C1[3];
            accL += lap2 * lap2;
            float lap3 = 6.f * d2C1[3] - d2C2[3] - d2C0[3]
                       - d2L1[3] - d2R1[3] - d2C1[2] - d2n1;
            accL += lap3 * lap3;
        }
    }

    #pragma unroll
    for (int t = 0; t < 4; t++) {
        d2C2[t] = d2C1[t]; d2C1[t] = d2C0[t];
        d2L1[t] = d2L0[t]; d2R1[t] = d2R0[t];
    }
    d2p1 = d2p0; d2n1 = d2n0;
}

__device__ __forceinline__ int clampi(int v) {
    return v < 0 ? 0 : (v > 255 ? 255 : v);
}

__global__ void __launch_bounds__(256, 1) kFused(const float* __restrict__ zg,
                                                 const float* __restrict__ tg,
                                                 float* __restrict__ out) {
    const int tid = threadIdx.x;
    const int k4  = tid & 15;
    const int col = tid >> 4;
    const int kk  = 4 * k4;

    int bid  = blockIdx.x;
    int jt   = bid & 15;
    int rest = bid >> 4;
    int seg  = rest % NSEG;
    int b    = rest / NSEG;
    int i0   = (seg * 256) / NSEG;
    int i1   = ((seg + 1) * 256) / NSEG;

    int j   = jt * 16 + col;
    int jmc = (j > 0)   ? j - 1 : 0;
    int jpc = (j < 255) ? j + 1 : 255;
    bool jdiv = (j < 255);
    bool jsm  = (j >= 1 && j <= 254);
    bool pfl  = ((k4 & 7) == 0);
    bool g1   = (k4 >= 1);
    bool l15  = (k4 < 15);

    const float* zb = zg + (size_t)b * CH + kk;
    const float* xb = tg + (size_t)b * 3 * CH + kk;
    const float* yb = xb + CH;
    const float* wb = yb + CH;
    size_t offj = (size_t)j * NK, offm = (size_t)jmc * NK, offp = (size_t)jpc * NK;

    __shared__ float shS[63], shQ[63];
    for (int t = tid; t < 63; t += 256) { shS[t] = 0.f; shQ[t] = 0.f; }
    __syncthreads();

    Row RA, RB;
    #pragma unroll
    for (int t = 0; t < 5; t++) { RA.zj[t] = 0.f; RA.zp[t] = 0.f; }
    #pragma unroll
    for (int t = 0; t < 4; t++) {
        RA.bxj[t] = RA.bxp[t] = RA.byj[t] = RA.byp[t] = RA.szr[t] = 0.f;
    }

    float d2C2[4] = {0,0,0,0}, d2C1[4] = {0,0,0,0};
    float d2L1[4] = {0,0,0,0}, d2R1[4] = {0,0,0,0};
    float d2p1 = 0.f, d2n1 = 0.f;
    float sS[4] = {0,0,0,0}, sQ[4] = {0,0,0,0};
    float accD = 0.f, accL = 0.f;

    // Software pipeline: loads for row gi+1 issue BEFORE compute of row gi,
    // giving a full step (~300 instrs) of load->use distance.
    int gi = i0 - 1;
    Raw W0 = load_row(clampi(gi), clampi(gi + 2), pfl,
                      zb, xb, yb, wb, offj, offm, offp);
    Raw W1;

    // Peel: gi = i0-1, i0 (guarded)
    W1 = load_row(clampi(gi + 1), clampi(gi + 3), pfl,
                  zb, xb, yb, wb, offj, offm, offp);
    compute<false>(RA, RB, W0, gi, i0, i1, jdiv, jsm, g1, l15, kk,
                   d2C2, d2C1, d2p1, d2n1, d2L1, d2R1, sS, sQ, accD, accL);
    gi++;
    W0 = load_row(clampi(gi + 1), clampi(gi + 3), pfl,
                  zb, xb, yb, wb, offj, offm, offp);
    compute<false>(RB, RA, W1, gi, i0, i1, jdiv, jsm, g1, l15, kk,
                   d2C2, d2C1, d2p1, d2n1, d2L1, d2R1, sS, sQ, accD, accL);
    gi++;

    // Interior pairs: gi in [i0+1, i1-1]
    #pragma unroll 1
    for (; gi + 1 <= i1 - 1; gi += 2) {
        W1 = load_row(gi + 1, clampi(gi + 3), pfl,
                      zb, xb, yb, wb, offj, offm, offp);
        compute<true>(RA, RB, W0, gi, i0, i1, jdiv, jsm, g1, l15, kk,
                      d2C2, d2C1, d2p1, d2n1, d2L1, d2R1, sS, sQ, accD, accL);
        W0 = load_row(clampi(gi + 2), clampi(gi + 4), pfl,
                      zb, xb, yb, wb, offj, offm, offp);
        compute<true>(RB, RA, W1, gi + 1, i0, i1, jdiv, jsm, g1, l15, kk,
                      d2C2, d2C1, d2p1, d2n1, d2L1, d2R1, sS, sQ, accD, accL);
    }
    if (gi <= i1 - 1) {
        // one leftover interior step, then final guarded (RB,RA)
        W1 = load_row(clampi(gi + 1), clampi(gi + 3), pfl,
                      zb, xb, yb, wb, offj, offm, offp);
        compute<true>(RA, RB, W0, gi, i0, i1, jdiv, jsm, g1, l15, kk,
                      d2C2, d2C1, d2p1, d2n1, d2L1, d2R1, sS, sQ, accD, accL);
        gi++;
        compute<false>(RB, RA, W1, gi, i0, i1, jdiv, jsm, g1, l15, kk,
                       d2C2, d2C1, d2p1, d2n1, d2L1, d2R1, sS, sQ, accD, accL);
    } else {
        // final guarded (RA,RB), data already staged in W0
        compute<false>(RA, RB, W0, gi, i0, i1, jdiv, jsm, g1, l15, kk,
                       d2C2, d2C1, d2p1, d2n1, d2L1, d2R1, sS, sQ, accD, accL);
    }

    // std bins: thread partials -> shared -> global (t=3 masked for lane 15)
    #pragma unroll
    for (int t = 0; t < 4; t++) if (kk + t < 63) {
        atomicAdd(&shS[kk + t], sS[t]);
        atomicAdd(&shQ[kk + t], sQ[t]);
    }
    __syncthreads();
    for (int t = tid; t < 63; t += 256) {
        atomicAdd(&g_sbin[b][t], shS[t]);
        atomicAdd(&g_qbin[b][t], shQ[t]);
    }

    // block reduce accD, accL
    {
        __shared__ float sa[8], sb2[8];
        const unsigned FM = 0xffffffffu;
        #pragma unroll
        for (int o = 16; o > 0; o >>= 1) {
            accD += __shfl_down_sync(FM, accD, o);
            accL += __shfl_down_sync(FM, accL, o);
        }
        int w = tid >> 5;
        if ((tid & 31) == 0) { sa[w] = accD; sb2[w] = accL; }
        __syncthreads();
        if (tid == 0) {
            float tD = 0.f, tL = 0.f;
            #pragma unroll
            for (int q = 0; q < 8; q++) { tD += sa[q]; tL += sb2[q]; }
            atomicAdd(&g_div_sum, (double)tD);
            atomicAdd(&g_smooth_sum, (double)tL);
        }
    }

    // last-block finalize + self-reset
    __threadfence();
    __shared__ bool islast;
    if (tid == 0) {
        unsigned v = atomicAdd(&g_done, 1u);
        islast = (v == gridDim.x - 1);
    }
    __syncthreads();
    if (islast) {
        if (tid == 0) g_done = 0;
        float v = 0.f;
        if (tid < 126) {
            float S = ((float*)g_sbin)[tid];
            float Q = ((float*)g_qbin)[tid];
            ((float*)g_sbin)[tid] = 0.f;
            ((float*)g_qbin)[tid] = 0.f;
            float var = (Q - S * S * (1.0f / 65536.0f)) * (1.0f / 65535.0f);
            v = sqrtf(fmaxf(var, 0.f));
        }
        __shared__ float sf[8];
        const unsigned FM = 0xffffffffu;
        #pragma unroll
        for (int o = 16; o > 0; o >>= 1) v += __shfl_down_sync(FM, v, o);
        if ((tid & 31) == 0) sf[tid >> 5] = v;
        __syncthreads();
        if (tid == 0) {
            float tot = 0.f;
            #pragma unroll
            for (int q = 0; q < 8; q++) tot += sf[q];
            double lstd = (double)(tot / 126.f);
            out[0] = (float)(g_div_sum * (1.0e9 / 8193150.0));
            out[1] = (float)(g_smooth_sum * (10.0 / 7870952.0) + lstd * 100.0);
            g_div_sum = 0.0;
            g_smooth_sum = 0.0;
        }
    }
}

extern "C" void kernel_launch(void* const* d_in, const int* in_sizes, int n_in,
                              void* d_out, int out_size) {
    const float* outp = (const float*)d_in[0];
    const float* tgt  = (const float*)d_in[1];
    if (n_in >= 2 && in_sizes[0] > in_sizes[1]) {
        const float* tmp = outp; outp = tgt; tgt = tmp;
    }
    float* out = (float*)d_out;

    kFused<<<NBLK, 256>>>(outp, tgt, out);
}

// round 17
// speedup vs baseline: 1.0621x; 1.0621x over previous
#include <cuda_runtime.h>
#include <cuda_bf16.h>

#define NK    64
#define PLANE (256 * 64)
#define CH    (256 * 256 * 64)
#define NSEG  9
#define NBLK  (2 * 16 * NSEG)   // 288

// Zero-initialized at module load; finalize self-resets them after each run,
// so the zero-state invariant holds across graph replays with no zero-kernel.
__device__ double g_div_sum;
__device__ double g_smooth_sum;
__device__ float  g_sbin[2][63];
__device__ float  g_qbin[2][63];
__device__ unsigned g_done;

__device__ __forceinline__ void pf_l2(const void* p) {
    asm volatile("prefetch.global.L2 [%0];" :: "l"(p));
}

__device__ __forceinline__ float cell_term(
    float p0a, float p0b, float p1a, float p1b,
    float q0a, float q0b, float q1a, float q1b,
    float sza, float szb, float Pva, float Pvb,
    float sxa, float sxb, float sya, float syb,
    float d00, float d01, float d10, float d11)
{
    float A1 = (p1a + p1b) * (d10 + d11);
    float A2 = (p0a + p0b) * (d00 + d01);
    float A3 = (q1a + q1b) * (d01 + d11);
    float A4 = (q0a + q0b) * (d00 + d10);
    float num = 0.125f * ((A1 - A2) + (A3 - A4))
              + 0.25f * (szb - sza) + (Pvb - Pva);
    float sxx = sxa + sxb;
    float syy = sya + syb;
    float szz = sza + szb;
    float den = 0.015625f * (sxx * sxx + syy * syy + szz * szz) + 1e-10f;
    return __fdividef(num * num, den);
}

struct Row {
    float bxj[4], bxp[4], byj[4], byp[4], szr[4];
    float zj[5], zp[5];
};

template<bool INT>
__device__ __forceinline__ void step(
    Row& P, Row& C, int gi, int i0, int i1, bool jdiv, bool jsm,
    bool pfl, bool g1, bool l15, int kk,
    const float* __restrict__ zb, const float* __restrict__ xb,
    const float* __restrict__ yb, const float* __restrict__ wb,
    size_t offj, size_t offm, size_t offp,
    float d2C2[4], float d2C1[4], float& d2p1, float& d2n1,
    float d2L1[4], float d2R1[4],
    float sS[4], float sQ[4], float& accD, float& accL)
{
    const unsigned FM = 0xffffffffu;
    int gic;
    if (INT) gic = gi;
    else     gic = gi < 0 ? 0 : (gi > 255 ? 255 : gi);
    size_t ro = (size_t)gic * PLANE;

    float4 zmf = *(const float4*)(zb + ro + offm);
    float4 zjf = *(const float4*)(zb + ro + offj);
    float4 zpf = *(const float4*)(zb + ro + offp);
    float4 xjf = *(const float4*)(xb + ro + offj);
    float4 xpf = *(const float4*)(xb + ro + offp);
    float4 yjf = *(const float4*)(yb + ro + offj);
    float4 ypf = *(const float4*)(yb + ro + offp);
    float4 wjf = *(const float4*)(wb + ro + offj);
    float4 wpf = *(const float4*)(wb + ro + offp);

    // L2 prefetch TWO rows ahead, CENTER columns only (1 lane per 128B line).
    // Halo columns are some neighboring block's center column — L2 is shared.
    {
        int gn = gi + 2; gn = gn > 255 ? 255 : (gn < 0 ? 0 : gn);
        size_t rn = (size_t)gn * PLANE;
        if (pfl) {
            pf_l2(zb + rn + offj);
            pf_l2(xb + rn + offj);
            pf_l2(yb + rn + offj);
            pf_l2(wb + rn + offj);
        }
    }

    float zm[5];
    zm[0] = zmf.x; zm[1] = zmf.y; zm[2] = zmf.z; zm[3] = zmf.w;
    C.zj[0] = zjf.x; C.zj[1] = zjf.y; C.zj[2] = zjf.z; C.zj[3] = zjf.w;
    C.zp[0] = zpf.x; C.zp[1] = zpf.y; C.zp[2] = zpf.z; C.zp[3] = zpf.w;
    C.bxj[0] = xjf.x; C.bxj[1] = xjf.y; C.bxj[2] = xjf.z; C.bxj[3] = xjf.w;
    C.bxp[0] = xpf.x; C.bxp[1] = xpf.y; C.bxp[2] = xpf.z; C.bxp[3] = xpf.w;
    C.byj[0] = yjf.x; C.byj[1] = yjf.y; C.byj[2] = yjf.z; C.byj[3] = yjf.w;
    C.byp[0] = ypf.x; C.byp[1] = ypf.y; C.byp[2] = ypf.z; C.byp[3] = ypf.w;
    C.szr[0] = wjf.x + wpf.x; C.szr[1] = wjf.y + wpf.y;
    C.szr[2] = wjf.z + wpf.z; C.szr[3] = wjf.w + wpf.w;

    zm[4]   = __shfl_down_sync(FM, zm[0],   1, 16);
    C.zj[4] = __shfl_down_sync(FM, C.zj[0], 1, 16);
    C.zp[4] = __shfl_down_sync(FM, C.zp[0], 1, 16);

    float dzc[4], d2C0[4], d2L0[4], d2R0[4];
    #pragma unroll
    for (int t = 0; t < 4; t++) {
        float dc = C.zj[t + 1] - C.zj[t]; dzc[t] = dc; d2C0[t] = dc * dc;
        float dl = zm[t + 1]   - zm[t];   d2L0[t] = dl * dl;
        float dr = C.zp[t + 1] - C.zp[t]; d2R0[t] = dr * dr;
    }
    float d2p0 = __shfl_up_sync(FM, d2C0[3], 1, 16);
    float d2n0 = __shfl_down_sync(FM, d2C0[0], 1, 16);

    // std accumulation: fully unconditional. Lane 15's t=3 partial is finite
    // garbage (width-16 shfl self-return) and is masked at the emit stage.
    bool ownC = INT ? true : (gi >= i0 && gi < i1);
    if (ownC) {
        #pragma unroll
        for (int t = 0; t < 4; t++) { sS[t] += dzc[t]; sQ[t] += d2C0[t]; }
    }

    // Per-plane quantities for the row pair (P, C), planes t = 0..3.
    float p0[4], p1[4], q0[4], q1[4], sz[4], Pv[4], sx[4], sy[4];
    #pragma unroll
    for (int t = 0; t < 4; t++) {
        p0[t] = P.bxj[t] + P.bxp[t];
        p1[t] = C.bxj[t] + C.bxp[t];
        q0[t] = P.byj[t] + C.byj[t];
        q1[t] = P.byp[t] + C.byp[t];
        sz[t] = P.szr[t] + C.szr[t];
        float A = P.zj[t] - C.zj[t];
        float B = P.zp[t] - C.zp[t];
        Pv[t] = (P.bxj[t] * A + P.bxp[t] * B + p1[t] * (A + B)
               + (C.byj[t] + C.byp[t] + P.byp[t]) * (C.zj[t] - C.zp[t])
               + (P.byj[t] + P.byp[t] + C.byp[t]) * (P.zj[t] - P.zp[t]))
               * (1.f / 6.f);
        sx[t] = p0[t] + p1[t];
        sy[t] = q0[t] + q1[t];
    }
    float p0_4 = __shfl_down_sync(FM, p0[0], 1, 16);
    float p1_4 = __shfl_down_sync(FM, p1[0], 1, 16);
    float q0_4 = __shfl_down_sync(FM, q0[0], 1, 16);
    float q1_4 = __shfl_down_sync(FM, q1[0], 1, 16);
    float sz_4 = __shfl_down_sync(FM, sz[0], 1, 16);
    float Pv_4 = __shfl_down_sync(FM, Pv[0], 1, 16);
    float sx_4 = p0_4 + p1_4;
    float sy_4 = q0_4 + q1_4;

    bool ownP = INT ? true : (gi - 1 >= i0 && gi - 1 < i1 && gi <= 255);
    if (ownP && jdiv) {
        // t = 0..2: always valid (kk+2 <= 62)
        #pragma unroll
        for (int t = 0; t < 3; t++) {
            float d00 = fabsf(P.zj[t + 1] - P.zj[t]);
            float d01 = fabsf(P.zp[t + 1] - P.zp[t]);
            float d10 = fabsf(dzc[t]);
            float d11 = fabsf(C.zp[t + 1] - C.zp[t]);
            accD += cell_term(p0[t], p0[t + 1], p1[t], p1[t + 1],
                              q0[t], q0[t + 1], q1[t], q1[t + 1],
                              sz[t], sz[t + 1], Pv[t], Pv[t + 1],
                              sx[t], sx[t + 1], sy[t], sy[t + 1],
                              d00, d01, d10, d11);
        }
        // t = 3: valid iff k4 < 15
        if (l15) {
            float d00 = fabsf(P.zj[4] - P.zj[3]);
            float d01 = fabsf(P.zp[4] - P.zp[3]);
            float d10 = fabsf(dzc[3]);
            float d11 = fabsf(C.zp[4] - C.zp[3]);
            accD += cell_term(p0[3], p0_4, p1[3], p1_4,
                              q0[3], q0_4, q1[3], q1_4,
                              sz[3], sz_4, Pv[3], Pv_4,
                              sx[3], sx_4, sy[3], sy_4,
                              d00, d01, d10, d11);
        }
    }

    int ic = gi - 1;
    bool smok;
    if (INT) smok = (ic >= 1) && (ic <= 254) && jsm;
    else     smok = (ic >= i0) && (ic < i1) && (ic >= 1) && (ic <= 254)
                    && (gi <= 255) && jsm;
    if (smok) {
        // t=0 needs k4>=1; t=1 always; t=2,3 need k4<15.
        if (g1) {
            float lap = 6.f * d2C1[0] - d2C2[0] - d2C0[0]
                      - d2L1[0] - d2R1[0] - d2p1 - d2C1[1];
            accL += lap * lap;
        }
        {
            float lap = 6.f * d2C1[1] - d2C2[1] - d2C0[1]
                      - d2L1[1] - d2R1[1] - d2C1[0] - d2C1[2];
            accL += lap * lap;
        }
        if (l15) {
            float lap2 = 6.f * d2C1[2] - d2C2[2] - d2C0[2]
                       - d2L1[2] - d2R1[2] - d2C1[1] - d2C1[3];
            accL += lap2 * lap2;
            float lap3 = 6.f * d2C1[3] - d2C2[3] - d2C0[3]
                       - d2L1[3] - d2R1[3] - d2C1[2] - d2n1;
            accL += lap3 * lap3;
        }
    }

    #pragma unroll
    for (int t = 0; t < 4; t++) {
        d2C2[t] = d2C1[t]; d2C1[t] = d2C0[t];
        d2L1[t] = d2L0[t]; d2R1[t] = d2R0[t];
    }
    d2p1 = d2p0; d2n1 = d2n0;
}

__global__ void __launch_bounds__(256, 2) kFused(const float* __restrict__ zg,
                                                 const float* __restrict__ tg,
                                                 float* __restrict__ out) {
    const int tid = threadIdx.x;
    const int k4  = tid & 15;
    const int col = tid >> 4;
    const int kk  = 4 * k4;

    int bid  = blockIdx.x;
    int jt   = bid & 15;
    int rest = bid >> 4;
    int seg  = rest % NSEG;
    int b    = rest / NSEG;
    int i0   = (seg * 256) / NSEG;
    int i1   = ((seg + 1) * 256) / NSEG;

    int j   = jt * 16 + col;
    int jmc = (j > 0)   ? j - 1 : 0;
    int jpc = (j < 255) ? j + 1 : 255;
    bool jdiv = (j < 255);
    bool jsm  = (j >= 1 && j <= 254);
    bool pfl  = ((k4 & 7) == 0);
    bool g1   = (k4 >= 1);
    bool l15  = (k4 < 15);

    const float* zb = zg + (size_t)b * CH + kk;
    const float* xb = tg + (size_t)b * 3 * CH + kk;
    const float* yb = xb + CH;
    const float* wb = yb + CH;
    size_t offj = (size_t)j * NK, offm = (size_t)jmc * NK, offp = (size_t)jpc * NK;

    __shared__ float shS[63], shQ[63];
    for (int t = tid; t < 63; t += 256) { shS[t] = 0.f; shQ[t] = 0.f; }
    __syncthreads();

    Row RA, RB;
    #pragma unroll
    for (int t = 0; t < 5; t++) { RA.zj[t] = 0.f; RA.zp[t] = 0.f; }
    #pragma unroll
    for (int t = 0; t < 4; t++) {
        RA.bxj[t] = RA.bxp[t] = RA.byj[t] = RA.byp[t] = RA.szr[t] = 0.f;
    }

    float d2C2[4] = {0,0,0,0}, d2C1[4] = {0,0,0,0};
    float d2L1[4] = {0,0,0,0}, d2R1[4] = {0,0,0,0};
    float d2p1 = 0.f, d2n1 = 0.f;
    float sS[4] = {0,0,0,0}, sQ[4] = {0,0,0,0};
    float accD = 0.f, accL = 0.f;

    // Peel: gi = i0-1, i0 (guarded)
    int gi = i0 - 1;
    step<false>(RA, RB, gi, i0, i1, jdiv, jsm, pfl, g1, l15, kk, zb, xb, yb, wb,
                offj, offm, offp, d2C2, d2C1, d2p1, d2n1, d2L1, d2R1,
                sS, sQ, accD, accL);
    gi++;
    step<false>(RB, RA, gi, i0, i1, jdiv, jsm, pfl, g1, l15, kk, zb, xb, yb, wb,
                offj, offm, offp, d2C2, d2C1, d2p1, d2n1, d2L1, d2R1,
                sS, sQ, accD, accL);
    gi++;

    // Interior: gi in [i0+1, i1-1], unconditional ownership
    #pragma unroll 1
    for (; gi + 1 <= i1 - 1; gi += 2) {
        step<true>(RA, RB, gi, i0, i1, jdiv, jsm, pfl, g1, l15, kk, zb, xb, yb, wb,
                   offj, offm, offp, d2C2, d2C1, d2p1, d2n1, d2L1, d2R1,
                   sS, sQ, accD, accL);
        step<true>(RB, RA, gi + 1, i0, i1, jdiv, jsm, pfl, g1, l15, kk, zb, xb, yb, wb,
                   offj, offm, offp, d2C2, d2C1, d2p1, d2n1, d2L1, d2R1,
                   sS, sQ, accD, accL);
    }
    bool flip = false;
    if (gi <= i1 - 1) {
        step<true>(RA, RB, gi, i0, i1, jdiv, jsm, pfl, g1, l15, kk, zb, xb, yb, wb,
                   offj, offm, offp, d2C2, d2C1, d2p1, d2n1, d2L1, d2R1,
                   sS, sQ, accD, accL);
        gi++;
        flip = true;
    }

    // Final: gi = i1 (guarded)
    if (!flip)
        step<false>(RA, RB, gi, i0, i1, jdiv, jsm, pfl, g1, l15, kk, zb, xb, yb, wb,
                    offj, offm, offp, d2C2, d2C1, d2p1, d2n1, d2L1, d2R1,
                    sS, sQ, accD, accL);
    else
        step<false>(RB, RA, gi, i0, i1, jdiv, jsm, pfl, g1, l15, kk, zb, xb, yb, wb,
                    offj, offm, offp, d2C2, d2C1, d2p1, d2n1, d2L1, d2R1,
                    sS, sQ, accD, accL);

    // std bins: thread partials -> shared -> global (t=3 masked for lane 15)
    #pragma unroll
    for (int t = 0; t < 4; t++) if (kk + t < 63) {
        atomicAdd(&shS[kk + t], sS[t]);
        atomicAdd(&shQ[kk + t], sQ[t]);
    }
    __syncthreads();
    for (int t = tid; t < 63; t += 256) {
        atomicAdd(&g_sbin[b][t], shS[t]);
        atomicAdd(&g_qbin[b][t], shQ[t]);
    }

    // block reduce accD, accL
    {
        __shared__ float sa[8], sb2[8];
        const unsigned FM = 0xffffffffu;
        #pragma unroll
        for (int o = 16; o > 0; o >>= 1) {
            accD += __shfl_down_sync(FM, accD, o);
            accL += __shfl_down_sync(FM, accL, o);
        }
        int w = tid >> 5;
        if ((tid & 31) == 0) { sa[w] = accD; sb2[w] = accL; }
        __syncthreads();
        if (tid == 0) {
            float tD = 0.f, tL = 0.f;
            #pragma unroll
            for (int q = 0; q < 8; q++) { tD += sa[q]; tL += sb2[q]; }
            atomicAdd(&g_div_sum, (double)tD);
            atomicAdd(&g_smooth_sum, (double)tL);
        }
    }

    // last-block finalize + self-reset (keeps zero-state invariant for the
    // next graph replay; module load provides the initial zeros)
    __threadfence();
    __shared__ bool islast;
    if (tid == 0) {
        unsigned v = atomicAdd(&g_done, 1u);
        islast = (v == gridDim.x - 1);
    }
    __syncthreads();
    if (islast) {
        if (tid == 0) g_done = 0;
        float v = 0.f;
        if (tid < 126) {
            float S = ((float*)g_sbin)[tid];
            float Q = ((float*)g_qbin)[tid];
            ((float*)g_sbin)[tid] = 0.f;      // self-reset after read
            ((float*)g_qbin)[tid] = 0.f;
            float var = (Q - S * S * (1.0f / 65536.0f)) * (1.0f / 65535.0f);
            v = sqrtf(fmaxf(var, 0.f));
        }
        __shared__ float sf[8];
        const unsigned FM = 0xffffffffu;
        #pragma unroll
        for (int o = 16; o > 0; o >>= 1) v += __shfl_down_sync(FM, v, o);
        if ((tid & 31) == 0) sf[tid >> 5] = v;
        __syncthreads();
        if (tid == 0) {
            float tot = 0.f;
            #pragma unroll
            for (int q = 0; q < 8; q++) tot += sf[q];
            double lstd = (double)(tot / 126.f);
            out[0] = (float)(g_div_sum * (1.0e9 / 8193150.0));
            out[1] = (float)(g_smooth_sum * (10.0 / 7870952.0) + lstd * 100.0);
            g_div_sum = 0.0;                  // self-reset after read
            g_smooth_sum = 0.0;
        }
    }
}

extern "C" void kernel_launch(void* const* d_in, const int* in_sizes, int n_in,
                              void* d_out, int out_size) {
    const float* outp = (const float*)d_in[0];
    const float* tgt  = (const float*)d_in[1];
    if (n_in >= 2 && in_sizes[0] > in_sizes[1]) {
        const float* tmp = outp; outp = tgt; tgt = tmp;
    }
    float* out = (float*)d_out;

    kFused<<<NBLK, 256>>>(outp, tgt, out);
}